// round 5
// baseline (speedup 1.0000x reference)
#include <cuda_runtime.h>
#include <cuda_bf16.h>
#include <cstdint>
#include <cstddef>

// Problem dims
#define BB   64
#define TT   2048
#define ID   1024
#define HD   1024
#define OD   512

// ---------------------------------------------------------------------------
// Scratch (__device__ globals: the sanctioned alloc-free workaround)
// ---------------------------------------------------------------------------
__device__ float         g_pre[(size_t)TT * BB * HD];        // [t][b][h]  (512 MB)
__device__ __nv_bfloat16 g_abf[(size_t)BB * TT * 3072];      // split X   (768 MB)
__device__ __nv_bfloat16 g_wbf[(size_t)HD * 3072];           // split W_ih  (6 MB)
__device__ float         g_part[2][8][BB * HD];              // K-split partials (4 MB)
__device__ float         g_h[BB * HD];                       // final hidden state
__device__ unsigned      g_flag[128];                        // barrier flags

// ---------------------------------------------------------------------------
// Generic-PTX helpers (safe for compute_103 target: no tcgen05/TMA)
// ---------------------------------------------------------------------------
__device__ __forceinline__ uint32_t smem_to_u32(const void* p) {
    uint32_t a;
    asm("{ .reg .u64 t; cvta.to.shared.u64 t, %1; cvt.u32.u64 %0, t; }"
        : "=r"(a) : "l"(p));
    return a;
}
__device__ __forceinline__ void cp16(uint32_t saddr, const void* g) {
    asm volatile("cp.async.cg.shared.global [%0], [%1], 16;"
                 :: "r"(saddr), "l"(g) : "memory");
}
#define CP_COMMIT() asm volatile("cp.async.commit_group;" ::: "memory")
#define CP_WAIT1()  asm volatile("cp.async.wait_group 1;" ::: "memory")
#define CP_WAIT0()  asm volatile("cp.async.wait_group 0;" ::: "memory")

__device__ __forceinline__ void ldsm_x4(uint32_t& r0, uint32_t& r1,
                                        uint32_t& r2, uint32_t& r3, uint32_t a) {
    asm volatile("ldmatrix.sync.aligned.m8n8.x4.shared.b16 {%0,%1,%2,%3}, [%4];"
                 : "=r"(r0), "=r"(r1), "=r"(r2), "=r"(r3) : "r"(a));
}
__device__ __forceinline__ void mma16816(float* c, const uint32_t* a,
                                         uint32_t b0, uint32_t b1) {
    asm volatile(
        "mma.sync.aligned.m16n8k16.row.col.f32.bf16.bf16.f32 "
        "{%0,%1,%2,%3}, {%4,%5,%6,%7}, {%8,%9}, {%0,%1,%2,%3};"
        : "+f"(c[0]), "+f"(c[1]), "+f"(c[2]), "+f"(c[3])
        : "r"(a[0]), "r"(a[1]), "r"(a[2]), "r"(a[3]), "r"(b0), "r"(b1));
}

// Accurate tanh built from EX2 (avoids tanh.approx under fast-math)
__device__ __forceinline__ float tanh_acc(float x) {
    float ax = fabsf(x);
    float e  = exp2f(ax * 2.885390081777927f);     // e^{2|x|}
    float r  = 1.0f - 2.0f / (e + 1.0f);
    return (x < 0.0f) ? -r : r;
}

// ---------------------------------------------------------------------------
// init: reset barrier flags
// ---------------------------------------------------------------------------
__global__ void init_kernel() {
    if (threadIdx.x < 128) g_flag[threadIdx.x] = 0u;
}

// ---------------------------------------------------------------------------
// bf16 2-term split precompute.
// A blocks along K': [hi | hi | lo]   W blocks: [hi | lo | hi]
//   => GEMM over K'=3072 computes Ah*Wh + Ah*Wl + Al*Wh  (drops Al*Wl ~ 2^-17)
// ---------------------------------------------------------------------------
__device__ __forceinline__ void split4(float4 v, ushort4& h, ushort4& l) {
    __nv_bfloat16 hx = __float2bfloat16(v.x);
    __nv_bfloat16 hy = __float2bfloat16(v.y);
    __nv_bfloat16 hz = __float2bfloat16(v.z);
    __nv_bfloat16 hw = __float2bfloat16(v.w);
    h.x = __bfloat16_as_ushort(hx); h.y = __bfloat16_as_ushort(hy);
    h.z = __bfloat16_as_ushort(hz); h.w = __bfloat16_as_ushort(hw);
    l.x = __bfloat16_as_ushort(__float2bfloat16(v.x - __bfloat162float(hx)));
    l.y = __bfloat16_as_ushort(__float2bfloat16(v.y - __bfloat162float(hy)));
    l.z = __bfloat16_as_ushort(__float2bfloat16(v.z - __bfloat162float(hz)));
    l.w = __bfloat16_as_ushort(__float2bfloat16(v.w - __bfloat162float(hw)));
}

__global__ __launch_bounds__(256) void split_x_kernel(const float* __restrict__ X) {
    const size_t n4 = (size_t)BB * TT * ID / 4;
    size_t stride = (size_t)gridDim.x * blockDim.x;
    for (size_t i = (size_t)blockIdx.x * blockDim.x + threadIdx.x; i < n4; i += stride) {
        size_t m  = i >> 8;
        int    k4 = (int)(i & 255);
        float4 v  = ((const float4*)X)[i];
        ushort4 h, l; split4(v, h, l);
        ushort4* row = (ushort4*)(g_abf + m * 3072);
        row[k4] = h; row[256 + k4] = h; row[512 + k4] = l;
    }
}

__global__ __launch_bounds__(256) void split_w_kernel(const float* __restrict__ W) {
    const size_t n4 = (size_t)HD * ID / 4;
    size_t stride = (size_t)gridDim.x * blockDim.x;
    for (size_t i = (size_t)blockIdx.x * blockDim.x + threadIdx.x; i < n4; i += stride) {
        size_t m  = i >> 8;
        int    k4 = (int)(i & 255);
        float4 v  = ((const float4*)W)[i];
        ushort4 h, l; split4(v, h, l);
        ushort4* row = (ushort4*)(g_wbf + m * 3072);
        row[k4] = h; row[256 + k4] = l; row[512 + k4] = h;
    }
}

// ---------------------------------------------------------------------------
// Phase 1 (tensor core, mma.sync bf16): pre = X @ W_ih^T + b_h.
// CTA tile 128x128, 8 warps (2m x 4n), warp tile 64x32 (mma m16n8k16).
// K'=3072 in 96 stages of 32; cp.async 2-stage pipeline; pad-40 smem rows.
// grid = (8, 1024): x = n-block fastest (A-tile L2 reuse, W resident).
// ---------------------------------------------------------------------------
#define P1_STRIDE 40                // bf16 elems per smem row (pad: 80B stride)
#define P1_NSTG   96                // 3072 / 32

__global__ __launch_bounds__(256, 2) void phase1_mma_kernel(const float* __restrict__ bh)
{
    __shared__ __nv_bfloat16 As[2][128 * P1_STRIDE];
    __shared__ __nv_bfloat16 Bs[2][128 * P1_STRIDE];

    const int tid  = threadIdx.x;
    const int bn   = blockIdx.x;          // 0..7
    const int bm   = blockIdx.y;          // 0..1023
    const int wid  = tid >> 5, lane = tid & 31;
    const int wm   = wid & 1;             // 0..1  (64 rows each)
    const int wn   = wid >> 1;            // 0..3  (32 cols each)

    const __nv_bfloat16* Ag = g_abf + (size_t)(bm * 128) * 3072;
    const __nv_bfloat16* Bg = g_wbf + (size_t)(bn * 128) * 3072;

    const uint32_t sA = smem_to_u32(As);
    const uint32_t sB = smem_to_u32(Bs);
    const int lr = tid >> 2, lq = tid & 3;   // loader: row, 16B-chunk

    float acc[4][4][4];
#pragma unroll
    for (int i = 0; i < 4; ++i)
#pragma unroll
        for (int j = 0; j < 4; ++j)
#pragma unroll
            for (int k = 0; k < 4; ++k) acc[i][j][k] = 0.0f;

#define LOAD_STAGE(kt, buf) do {                                                  \
    const __nv_bfloat16* ag = Ag + (size_t)lr * 3072 + (kt) * 32 + lq * 8;        \
    const __nv_bfloat16* bg = Bg + (size_t)lr * 3072 + (kt) * 32 + lq * 8;        \
    uint32_t da = sA + (uint32_t)(((buf) * 128 + lr) * P1_STRIDE + lq * 8) * 2;   \
    uint32_t db = sB + (uint32_t)(((buf) * 128 + lr) * P1_STRIDE + lq * 8) * 2;   \
    cp16(da, ag); cp16(da + 64 * P1_STRIDE * 2, ag + (size_t)64 * 3072);          \
    cp16(db, bg); cp16(db + 64 * P1_STRIDE * 2, bg + (size_t)64 * 3072);          \
} while (0)

    LOAD_STAGE(0, 0); CP_COMMIT();
    LOAD_STAGE(1, 1); CP_COMMIT();

    const int lrow  = lane & 15;
    const int lhalf = lane >> 4;

    for (int kt = 0; kt < P1_NSTG; ++kt) {
        if (kt < P1_NSTG - 1) { CP_WAIT1(); } else { CP_WAIT0(); }
        __syncthreads();

        const int buf = kt & 1;
        const uint32_t abase = sA + (uint32_t)(buf * 128 * P1_STRIDE) * 2;
        const uint32_t bbase = sB + (uint32_t)(buf * 128 * P1_STRIDE) * 2;

#pragma unroll
        for (int ks = 0; ks < 2; ++ks) {
            uint32_t a[4][4];
#pragma unroll
            for (int mt = 0; mt < 4; ++mt) {
                uint32_t ad = abase +
                    (uint32_t)((wm * 64 + mt * 16 + lrow) * P1_STRIDE + ks * 16 + lhalf * 8) * 2;
                ldsm_x4(a[mt][0], a[mt][1], a[mt][2], a[mt][3], ad);
            }
            uint32_t bf[2][4];
#pragma unroll
            for (int bp = 0; bp < 2; ++bp) {
                uint32_t bd = bbase +
                    (uint32_t)((wn * 32 + bp * 16 + lrow) * P1_STRIDE + ks * 16 + lhalf * 8) * 2;
                ldsm_x4(bf[bp][0], bf[bp][1], bf[bp][2], bf[bp][3], bd);
            }
#pragma unroll
            for (int mt = 0; mt < 4; ++mt)
#pragma unroll
                for (int nt = 0; nt < 4; ++nt)
                    mma16816(acc[mt][nt], a[mt],
                             bf[nt >> 1][nt & 1], bf[nt >> 1][(nt & 1) + 2]);
        }
        __syncthreads();
        if (kt + 2 < P1_NSTG) { LOAD_STAGE(kt + 2, buf); CP_COMMIT(); }
    }
#undef LOAD_STAGE

    // Epilogue: c-frag rows = lane>>2 (+8), cols = (lane&3)*2 (+1); remap to
    // t-major g_pre and add bias.
    const int col0 = bn * 128 + wn * 32;
#pragma unroll
    for (int mt = 0; mt < 4; ++mt) {
#pragma unroll
        for (int half = 0; half < 2; ++half) {
            int m  = bm * 128 + wm * 64 + mt * 16 + (lane >> 2) + half * 8;
            int b_ = m >> 11;
            int t_ = m & (TT - 1);
            float* orow = g_pre + ((size_t)t_ * BB + b_) * HD;
#pragma unroll
            for (int nt = 0; nt < 4; ++nt) {
                int c = col0 + nt * 8 + (lane & 3) * 2;
                float2 v;
                v.x = acc[mt][nt][half * 2 + 0] + __ldg(bh + c);
                v.y = acc[mt][nt][half * 2 + 1] + __ldg(bh + c + 1);
                *(float2*)(orow + c) = v;
            }
        }
    }
}

// ---------------------------------------------------------------------------
// Phase 2: persistent recurrence kernel (fp32 FFMA).
// 128 CTAs = 4 batch-groups(16) x 4 col-groups(256) x 8 K-splits(128).
// W_hh slice resident in SMEM (128 KB). Flag-based grid barrier (no contended
// atomics).
// ---------------------------------------------------------------------------
#define RK_NCTA 128
#define RK_SMEM_BYTES ((128 * 256 + 128 * 16) * 4)   // 139264

__global__ __launch_bounds__(128) void recur_kernel(const float* __restrict__ Whh)
{
    extern __shared__ float fsm[];
    float* Ws = fsm;                // [k=128][n=256]
    float* Hs = fsm + 128 * 256;    // [k=128][m=16]

    const int tid = threadIdx.x;
    const int cta = blockIdx.x;
    const int bg  = cta & 3;
    const int cg  = (cta >> 2) & 3;
    const int ks  = cta >> 4;

    for (int e = tid; e < 128 * 256; e += 128) {
        int n = e >> 7, k = e & 127;
        Ws[k * 256 + n] = Whh[(size_t)(cg * 256 + n) * HD + (ks * 128 + k)];
    }
    __syncthreads();

    const int tm = tid >> 6;
    const int tn = tid & 63;
    const float4* Ws4 = (const float4*)Ws;

    for (int t = 0; t < TT; ++t) {
        const int p = t & 1;

        if (t == 0) {
            for (int e = tid; e < 2048; e += 128) Hs[e] = 0.0f;
        } else {
            const float* pre = g_pre + (size_t)(t - 1) * BB * HD;
            const int q = 1 - p;
            for (int e = tid; e < 2048; e += 128) {
                int m = e >> 7, k = e & 127;
                size_t idx = (size_t)(bg * 16 + m) * HD + (size_t)(ks * 128 + k);
                float s = pre[idx];
#pragma unroll
                for (int sp = 0; sp < 8; ++sp) s += g_part[q][sp][idx];
                Hs[k * 16 + m] = tanh_acc(s);
            }
        }
        __syncthreads();

        float acc[8][4];
#pragma unroll
        for (int i = 0; i < 8; ++i)
#pragma unroll
            for (int j = 0; j < 4; ++j) acc[i][j] = 0.0f;

#pragma unroll 4
        for (int k = 0; k < 128; ++k) {
            float4 wv = Ws4[(k << 6) + tn];
            const float* hp = &Hs[(k << 4) + (tm << 3)];
            float4 ha = *(const float4*)(hp);
            float4 hb = *(const float4*)(hp + 4);
            float hv[8] = {ha.x, ha.y, ha.z, ha.w, hb.x, hb.y, hb.z, hb.w};
            float wf[4] = {wv.x, wv.y, wv.z, wv.w};
#pragma unroll
            for (int i = 0; i < 8; ++i)
#pragma unroll
                for (int j = 0; j < 4; ++j)
                    acc[i][j] = fmaf(hv[i], wf[j], acc[i][j]);
        }

        float* po = g_part[p][ks] + (size_t)(bg * 16 + tm * 8) * HD + cg * 256 + tn * 4;
#pragma unroll
        for (int i = 0; i < 8; ++i)
            *(float4*)(po + (size_t)i * HD) =
                make_float4(acc[i][0], acc[i][1], acc[i][2], acc[i][3]);

        // flag-based grid barrier (all 128 CTAs co-resident)
        const unsigned t1 = (unsigned)(t + 1);
        __threadfence();
        __syncthreads();
        if (tid == 0) ((volatile unsigned*)g_flag)[cta] = t1;
        while (((volatile unsigned*)g_flag)[tid] < t1) { }
        __syncthreads();
        __threadfence();
    }

    if (ks == 0) {
        const float* pre = g_pre + (size_t)(TT - 1) * BB * HD;
        const int q = (TT - 1) & 1;
        for (int e = tid; e < 16 * 256; e += 128) {
            int m = e >> 8, c = e & 255;
            size_t idx = (size_t)(bg * 16 + m) * HD + (size_t)(cg * 256 + c);
            float s = pre[idx];
#pragma unroll
            for (int sp = 0; sp < 8; ++sp) s += g_part[q][sp][idx];
            g_h[idx] = tanh_acc(s);
        }
    }
}

// ---------------------------------------------------------------------------
// Phase 3: out[b][o] = h_T[b] . W_out[o] + b_out[o]   grid (64, 4)
// ---------------------------------------------------------------------------
__global__ __launch_bounds__(128) void out_kernel(
    const float* __restrict__ Wout, const float* __restrict__ bout,
    float* __restrict__ out)
{
    __shared__ float hs[HD];
    const int b = blockIdx.x, bo = blockIdx.y, tid = threadIdx.x;
    for (int i = tid; i < HD; i += 128) hs[i] = g_h[(size_t)b * HD + i];
    __syncthreads();
    const int o = bo * 128 + tid;
    const float* w = Wout + (size_t)o * HD;
    float s0 = 0.f, s1 = 0.f, s2 = 0.f, s3 = 0.f;
    for (int k = 0; k < HD; k += 4) {
        float4 wv = *(const float4*)(w + k);
        s0 = fmaf(hs[k + 0], wv.x, s0);
        s1 = fmaf(hs[k + 1], wv.y, s1);
        s2 = fmaf(hs[k + 2], wv.z, s2);
        s3 = fmaf(hs[k + 3], wv.w, s3);
    }
    out[(size_t)b * OD + o] = (s0 + s1) + (s2 + s3) + bout[o];
}

// ---------------------------------------------------------------------------
extern "C" void kernel_launch(void* const* d_in, const int* in_sizes, int n_in,
                              void* d_out, int out_size)
{
    (void)in_sizes; (void)n_in; (void)out_size;
    const float* x    = (const float*)d_in[0];
    const float* Wih  = (const float*)d_in[1];
    const float* Whh  = (const float*)d_in[2];
    const float* bh   = (const float*)d_in[3];
    const float* Wout = (const float*)d_in[4];
    const float* bout = (const float*)d_in[5];
    float* out = (float*)d_out;

    cudaFuncSetAttribute(recur_kernel,
                         cudaFuncAttributeMaxDynamicSharedMemorySize, RK_SMEM_BYTES);

    init_kernel<<<1, 128>>>();
    split_w_kernel<<<256, 256>>>(Wih);
    split_x_kernel<<<2048, 256>>>(x);

    dim3 g1(8, 1024);                       // (HD/128, M/128) — n-block fastest
    phase1_mma_kernel<<<g1, 256>>>(bh);

    recur_kernel<<<RK_NCTA, 128, RK_SMEM_BYTES>>>(Whh);

    out_kernel<<<dim3(BB, 4), 128>>>(Wout, bout, out);
}

// round 6
// speedup vs baseline: 3.2872x; 3.2872x over previous
#include <cuda_runtime.h>
#include <cuda_bf16.h>
#include <cstdint>
#include <cstddef>

// Problem dims
#define BB   64
#define TT   2048
#define ID   1024
#define HD   1024
#define OD   512

// ---------------------------------------------------------------------------
// Scratch (__device__ globals)
// ---------------------------------------------------------------------------
__device__ float         g_pre[(size_t)TT * BB * HD];        // [t][b][h]  (512 MB)
__device__ __nv_bfloat16 g_abf[(size_t)BB * TT * 3072];      // split X   (768 MB)
__device__ __nv_bfloat16 g_wbf[(size_t)HD * 3072];           // split W_ih  (6 MB)
__device__ __nv_bfloat16 g_hbf[2][2][BB][HD];                // h double-buf, hi/lo (0.5 MB)
__device__ float         g_h[BB * HD];                       // final hidden state
__device__ unsigned      g_cnt2[4][32];                      // per-group arrival counters (padded)
__device__ unsigned      g_gen2[4][32];                      // per-group generation words (padded)

// ---------------------------------------------------------------------------
// Generic-PTX helpers (safe for compute_103 target: no tcgen05/TMA)
// ---------------------------------------------------------------------------
__device__ __forceinline__ uint32_t smem_to_u32(const void* p) {
    uint32_t a;
    asm("{ .reg .u64 t; cvta.to.shared.u64 t, %1; cvt.u32.u64 %0, t; }"
        : "=r"(a) : "l"(p));
    return a;
}
__device__ __forceinline__ void cp16(uint32_t saddr, const void* g) {
    asm volatile("cp.async.cg.shared.global [%0], [%1], 16;"
                 :: "r"(saddr), "l"(g) : "memory");
}
#define CP_COMMIT() asm volatile("cp.async.commit_group;" ::: "memory")
#define CP_WAIT1()  asm volatile("cp.async.wait_group 1;" ::: "memory")
#define CP_WAIT0()  asm volatile("cp.async.wait_group 0;" ::: "memory")

__device__ __forceinline__ void ldsm_x4(uint32_t& r0, uint32_t& r1,
                                        uint32_t& r2, uint32_t& r3, uint32_t a) {
    asm volatile("ldmatrix.sync.aligned.m8n8.x4.shared.b16 {%0,%1,%2,%3}, [%4];"
                 : "=r"(r0), "=r"(r1), "=r"(r2), "=r"(r3) : "r"(a));
}
__device__ __forceinline__ void ldsm_x2(uint32_t& r0, uint32_t& r1, uint32_t a) {
    asm volatile("ldmatrix.sync.aligned.m8n8.x2.shared.b16 {%0,%1}, [%2];"
                 : "=r"(r0), "=r"(r1) : "r"(a));
}
__device__ __forceinline__ void mma16816(float* c, const uint32_t* a,
                                         uint32_t b0, uint32_t b1) {
    asm volatile(
        "mma.sync.aligned.m16n8k16.row.col.f32.bf16.bf16.f32 "
        "{%0,%1,%2,%3}, {%4,%5,%6,%7}, {%8,%9}, {%0,%1,%2,%3};"
        : "+f"(c[0]), "+f"(c[1]), "+f"(c[2]), "+f"(c[3])
        : "r"(a[0]), "r"(a[1]), "r"(a[2]), "r"(a[3]), "r"(b0), "r"(b1));
}

// Accurate tanh built from EX2 (avoids tanh.approx under fast-math)
__device__ __forceinline__ float tanh_acc(float x) {
    float ax = fabsf(x);
    float e  = exp2f(ax * 2.885390081777927f);     // e^{2|x|}
    float r  = 1.0f - 2.0f / (e + 1.0f);
    return (x < 0.0f) ? -r : r;
}

// ---------------------------------------------------------------------------
// init: zero h buffer 0 (hi+lo) and barrier state.  grid 256x256.
// ---------------------------------------------------------------------------
__global__ __launch_bounds__(256) void init_kernel() {
    unsigned i = blockIdx.x * 256u + threadIdx.x;          // 0..65535
    ((uint32_t*)g_hbf)[i] = 0u;                            // 2*64*1024 bf16 = 65536 u32
    if (i < 128) { ((unsigned*)g_cnt2)[i] = 0u; ((unsigned*)g_gen2)[i] = 0u; }
}

// ---------------------------------------------------------------------------
// bf16 2-term split precompute for phase1.
// A blocks along K': [hi | hi | lo]   W blocks: [hi | lo | hi]
// ---------------------------------------------------------------------------
__device__ __forceinline__ void split4(float4 v, ushort4& h, ushort4& l) {
    __nv_bfloat16 hx = __float2bfloat16(v.x);
    __nv_bfloat16 hy = __float2bfloat16(v.y);
    __nv_bfloat16 hz = __float2bfloat16(v.z);
    __nv_bfloat16 hw = __float2bfloat16(v.w);
    h.x = __bfloat16_as_ushort(hx); h.y = __bfloat16_as_ushort(hy);
    h.z = __bfloat16_as_ushort(hz); h.w = __bfloat16_as_ushort(hw);
    l.x = __bfloat16_as_ushort(__float2bfloat16(v.x - __bfloat162float(hx)));
    l.y = __bfloat16_as_ushort(__float2bfloat16(v.y - __bfloat162float(hy)));
    l.z = __bfloat16_as_ushort(__float2bfloat16(v.z - __bfloat162float(hz)));
    l.w = __bfloat16_as_ushort(__float2bfloat16(v.w - __bfloat162float(hw)));
}

__global__ __launch_bounds__(256) void split_x_kernel(const float* __restrict__ X) {
    const size_t n4 = (size_t)BB * TT * ID / 4;
    size_t stride = (size_t)gridDim.x * blockDim.x;
    for (size_t i = (size_t)blockIdx.x * blockDim.x + threadIdx.x; i < n4; i += stride) {
        size_t m  = i >> 8;
        int    k4 = (int)(i & 255);
        float4 v  = ((const float4*)X)[i];
        ushort4 h, l; split4(v, h, l);
        ushort4* row = (ushort4*)(g_abf + m * 3072);
        row[k4] = h; row[256 + k4] = h; row[512 + k4] = l;
    }
}

__global__ __launch_bounds__(256) void split_w_kernel(const float* __restrict__ W) {
    const size_t n4 = (size_t)HD * ID / 4;
    size_t stride = (size_t)gridDim.x * blockDim.x;
    for (size_t i = (size_t)blockIdx.x * blockDim.x + threadIdx.x; i < n4; i += stride) {
        size_t m  = i >> 8;
        int    k4 = (int)(i & 255);
        float4 v  = ((const float4*)W)[i];
        ushort4 h, l; split4(v, h, l);
        ushort4* row = (ushort4*)(g_wbf + m * 3072);
        row[k4] = h; row[256 + k4] = l; row[512 + k4] = h;
    }
}

// ---------------------------------------------------------------------------
// Phase 1 (mma.sync bf16): pre = X @ W_ih^T + b_h.  (unchanged from R5)
// ---------------------------------------------------------------------------
#define P1_STRIDE 40
#define P1_NSTG   96

__global__ __launch_bounds__(256, 2) void phase1_mma_kernel(const float* __restrict__ bh)
{
    __shared__ __nv_bfloat16 As[2][128 * P1_STRIDE];
    __shared__ __nv_bfloat16 Bs[2][128 * P1_STRIDE];

    const int tid  = threadIdx.x;
    const int bn   = blockIdx.x;          // 0..7
    const int bm   = blockIdx.y;          // 0..1023
    const int wid  = tid >> 5, lane = tid & 31;
    const int wm   = wid & 1;
    const int wn   = wid >> 1;

    const __nv_bfloat16* Ag = g_abf + (size_t)(bm * 128) * 3072;
    const __nv_bfloat16* Bg = g_wbf + (size_t)(bn * 128) * 3072;

    const uint32_t sA = smem_to_u32(As);
    const uint32_t sB = smem_to_u32(Bs);
    const int lr = tid >> 2, lq = tid & 3;

    float acc[4][4][4];
#pragma unroll
    for (int i = 0; i < 4; ++i)
#pragma unroll
        for (int j = 0; j < 4; ++j)
#pragma unroll
            for (int k = 0; k < 4; ++k) acc[i][j][k] = 0.0f;

#define LOAD_STAGE(kt, buf) do {                                                  \
    const __nv_bfloat16* ag = Ag + (size_t)lr * 3072 + (kt) * 32 + lq * 8;        \
    const __nv_bfloat16* bg = Bg + (size_t)lr * 3072 + (kt) * 32 + lq * 8;        \
    uint32_t da = sA + (uint32_t)(((buf) * 128 + lr) * P1_STRIDE + lq * 8) * 2;   \
    uint32_t db = sB + (uint32_t)(((buf) * 128 + lr) * P1_STRIDE + lq * 8) * 2;   \
    cp16(da, ag); cp16(da + 64 * P1_STRIDE * 2, ag + (size_t)64 * 3072);          \
    cp16(db, bg); cp16(db + 64 * P1_STRIDE * 2, bg + (size_t)64 * 3072);          \
} while (0)

    LOAD_STAGE(0, 0); CP_COMMIT();
    LOAD_STAGE(1, 1); CP_COMMIT();

    const int lrow  = lane & 15;
    const int lhalf = lane >> 4;

    for (int kt = 0; kt < P1_NSTG; ++kt) {
        if (kt < P1_NSTG - 1) { CP_WAIT1(); } else { CP_WAIT0(); }
        __syncthreads();

        const int buf = kt & 1;
        const uint32_t abase = sA + (uint32_t)(buf * 128 * P1_STRIDE) * 2;
        const uint32_t bbase = sB + (uint32_t)(buf * 128 * P1_STRIDE) * 2;

#pragma unroll
        for (int ks = 0; ks < 2; ++ks) {
            uint32_t a[4][4];
#pragma unroll
            for (int mt = 0; mt < 4; ++mt) {
                uint32_t ad = abase +
                    (uint32_t)((wm * 64 + mt * 16 + lrow) * P1_STRIDE + ks * 16 + lhalf * 8) * 2;
                ldsm_x4(a[mt][0], a[mt][1], a[mt][2], a[mt][3], ad);
            }
            uint32_t bf[2][4];
#pragma unroll
            for (int bp = 0; bp < 2; ++bp) {
                uint32_t bd = bbase +
                    (uint32_t)((wn * 32 + bp * 16 + lrow) * P1_STRIDE + ks * 16 + lhalf * 8) * 2;
                ldsm_x4(bf[bp][0], bf[bp][1], bf[bp][2], bf[bp][3], bd);
            }
#pragma unroll
            for (int mt = 0; mt < 4; ++mt)
#pragma unroll
                for (int nt = 0; nt < 4; ++nt)
                    mma16816(acc[mt][nt], a[mt],
                             bf[nt >> 1][nt & 1], bf[nt >> 1][(nt & 1) + 2]);
        }
        __syncthreads();
        if (kt + 2 < P1_NSTG) { LOAD_STAGE(kt + 2, buf); CP_COMMIT(); }
    }
#undef LOAD_STAGE

    const int col0 = bn * 128 + wn * 32;
#pragma unroll
    for (int mt = 0; mt < 4; ++mt) {
#pragma unroll
        for (int half = 0; half < 2; ++half) {
            int m  = bm * 128 + wm * 64 + mt * 16 + (lane >> 2) + half * 8;
            int b_ = m >> 11;
            int t_ = m & (TT - 1);
            float* orow = g_pre + ((size_t)t_ * BB + b_) * HD;
#pragma unroll
            for (int nt = 0; nt < 4; ++nt) {
                int c = col0 + nt * 8 + (lane & 3) * 2;
                float2 v;
                v.x = acc[mt][nt][half * 2 + 0] + __ldg(bh + c);
                v.y = acc[mt][nt][half * 2 + 1] + __ldg(bh + c + 1);
                *(float2*)(orow + c) = v;
            }
        }
    }
}

// ---------------------------------------------------------------------------
// Phase 2: persistent recurrence, HMMA split-bf16, NO K-split.
// 128 CTAs = 4 batch-groups(16 rows) x 32 col-groups(32 cols).
// SMEM: W_hh slice hi/lo [32 x 1024] bf16 (persistent) + h slice hi/lo
// [16 x 1024] bf16 (reloaded per step). 128 threads = 4 warps, each warp
// owns one n8 column tile (m16n8 output).
// Per-group barrier: 1 atomicAdd arrival + leader gen-store + tid==0 poll.
// ---------------------------------------------------------------------------
#define W_STRIDE 1032                       // bf16 elems per smem row (+16B pad)
#define SM_WHI   0
#define SM_WLO   (32 * W_STRIDE)
#define SM_HHI   (64 * W_STRIDE)
#define SM_HLO   (80 * W_STRIDE)
#define R2_SMEM  (96 * W_STRIDE * 2)        // 198144 bytes

__global__ __launch_bounds__(128, 1) void recur2_kernel(const float* __restrict__ Whh)
{
    extern __shared__ __nv_bfloat16 sm[];
    const int tid  = threadIdx.x;
    const int lane = tid & 31, wid = tid >> 5;
    const int bg   = blockIdx.x >> 5;       // 0..3
    const int cg   = blockIdx.x & 31;       // 0..31
    const uint32_t sb = smem_to_u32(sm);

    // ---- load persistent W_hh slice, split hi/lo ----
    for (int e = tid; e < 32 * 1024; e += 128) {
        int n = e >> 10, k = e & 1023;
        float v = Whh[(size_t)(cg * 32 + n) * HD + k];
        __nv_bfloat16 h = __float2bfloat16(v);
        sm[SM_WHI + n * W_STRIDE + k] = h;
        sm[SM_WLO + n * W_STRIDE + k] = __float2bfloat16(v - __bfloat162float(h));
    }

    // fragment addresses (byte offsets added per pass/k-step)
    const uint32_t aLane = sb + (uint32_t)((lane & 15) * W_STRIDE + (lane >> 4) * 8) * 2;
    const uint32_t bLane = sb + (uint32_t)((wid * 8 + (lane & 7)) * W_STRIDE
                                           + ((lane >> 3) & 1) * 8) * 2;

    // epilogue coordinates
    const int row0 = bg * 16 + (lane >> 2);
    const int c0   = cg * 32 + wid * 8 + (lane & 3) * 2;

    volatile unsigned* genw = &g_gen2[bg][0];

    __syncthreads();

    for (int t = 0; t < TT; ++t) {
        const int r = t & 1, w = 1 - r;

        // ---- load h slice (hi+lo) into smem via cp.async ----
#pragma unroll
        for (int s = 0; s < 2; ++s) {
            const __nv_bfloat16* src = &g_hbf[r][s][bg * 16][0];
            uint32_t dst = sb + (uint32_t)((s ? SM_HLO : SM_HHI)) * 2;
#pragma unroll
            for (int i = 0; i < 16; ++i) {
                int chunk = tid + i * 128;          // 0..2047
                int row = chunk >> 7, c8 = (chunk & 127) * 8;
                cp16(dst + (uint32_t)(row * W_STRIDE + c8) * 2, src + row * 1024 + c8);
            }
        }
        CP_COMMIT(); CP_WAIT0();
        __syncthreads();

        // prefetch pre (hidden behind the MMA loop)
        const float2 pv0 = *(const float2*)&g_pre[((size_t)t * BB + row0) * HD + c0];
        const float2 pv1 = *(const float2*)&g_pre[((size_t)t * BB + row0 + 8) * HD + c0];

        // ---- 3-pass split GEMM: Ah*Wh + Ah*Wl + Al*Wh ----
        float accs[4][4];
#pragma unroll
        for (int i = 0; i < 4; ++i)
#pragma unroll
            for (int j = 0; j < 4; ++j) accs[i][j] = 0.0f;

#pragma unroll
        for (int p3 = 0; p3 < 3; ++p3) {
            const uint32_t Aoff = (uint32_t)((p3 < 2) ? SM_HHI : SM_HLO) * 2;
            const uint32_t Woff = (uint32_t)((p3 == 1) ? SM_WLO : SM_WHI) * 2;
#pragma unroll 4
            for (int ks = 0; ks < 64; ++ks) {
                uint32_t a[4], b0, b1;
                ldsm_x4(a[0], a[1], a[2], a[3], aLane + Aoff + ks * 32);
                ldsm_x2(b0, b1, bLane + Woff + ks * 32);
                mma16816(accs[ks & 3], a, b0, b1);
            }
        }
        float c[4];
#pragma unroll
        for (int j = 0; j < 4; ++j)
            c[j] = (accs[0][j] + accs[1][j]) + (accs[2][j] + accs[3][j]);

        // ---- epilogue: + pre, tanh, split to bf16 hi/lo, store ----
        {
            float v0 = tanh_acc(c[0] + pv0.x);
            float v1 = tanh_acc(c[1] + pv0.y);
            float v2 = tanh_acc(c[2] + pv1.x);
            float v3 = tanh_acc(c[3] + pv1.y);

            __nv_bfloat16 h0 = __float2bfloat16(v0), h1 = __float2bfloat16(v1);
            __nv_bfloat16 h2 = __float2bfloat16(v2), h3 = __float2bfloat16(v3);
            __nv_bfloat162 hi01; hi01.x = h0; hi01.y = h1;
            __nv_bfloat162 hi23; hi23.x = h2; hi23.y = h3;
            __nv_bfloat162 lo01, lo23;
            lo01.x = __float2bfloat16(v0 - __bfloat162float(h0));
            lo01.y = __float2bfloat16(v1 - __bfloat162float(h1));
            lo23.x = __float2bfloat16(v2 - __bfloat162float(h2));
            lo23.y = __float2bfloat16(v3 - __bfloat162float(h3));

            *(__nv_bfloat162*)&g_hbf[w][0][row0][c0]     = hi01;
            *(__nv_bfloat162*)&g_hbf[w][1][row0][c0]     = lo01;
            *(__nv_bfloat162*)&g_hbf[w][0][row0 + 8][c0] = hi23;
            *(__nv_bfloat162*)&g_hbf[w][1][row0 + 8][c0] = lo23;

            if (t == TT - 1) {
                *(float2*)&g_h[(size_t)row0 * HD + c0]       = make_float2(v0, v1);
                *(float2*)&g_h[(size_t)(row0 + 8) * HD + c0] = make_float2(v2, v3);
            }
        }

        // ---- per-group barrier (32 CTAs): single poller per CTA ----
        __threadfence();
        __syncthreads();
        if (tid == 0) {
            const unsigned t1 = (unsigned)(t + 1);
            unsigned prev = atomicAdd(&g_cnt2[bg][0], 1u);
            if (prev == 31u) {
                atomicExch(&g_cnt2[bg][0], 0u);
                __threadfence();
                *genw = t1;
            } else {
                while (*genw < t1) { }
            }
            __threadfence();
        }
        __syncthreads();
    }
}

// ---------------------------------------------------------------------------
// Phase 3: out[b][o] = h_T[b] . W_out[o] + b_out[o]   grid (64, 4)
// ---------------------------------------------------------------------------
__global__ __launch_bounds__(128) void out_kernel(
    const float* __restrict__ Wout, const float* __restrict__ bout,
    float* __restrict__ out)
{
    __shared__ float hs[HD];
    const int b = blockIdx.x, bo = blockIdx.y, tid = threadIdx.x;
    for (int i = tid; i < HD; i += 128) hs[i] = g_h[(size_t)b * HD + i];
    __syncthreads();
    const int o = bo * 128 + tid;
    const float* w = Wout + (size_t)o * HD;
    float s0 = 0.f, s1 = 0.f, s2 = 0.f, s3 = 0.f;
    for (int k = 0; k < HD; k += 4) {
        float4 wv = *(const float4*)(w + k);
        s0 = fmaf(hs[k + 0], wv.x, s0);
        s1 = fmaf(hs[k + 1], wv.y, s1);
        s2 = fmaf(hs[k + 2], wv.z, s2);
        s3 = fmaf(hs[k + 3], wv.w, s3);
    }
    out[(size_t)b * OD + o] = (s0 + s1) + (s2 + s3) + bout[o];
}

// ---------------------------------------------------------------------------
extern "C" void kernel_launch(void* const* d_in, const int* in_sizes, int n_in,
                              void* d_out, int out_size)
{
    (void)in_sizes; (void)n_in; (void)out_size;
    const float* x    = (const float*)d_in[0];
    const float* Wih  = (const float*)d_in[1];
    const float* Whh  = (const float*)d_in[2];
    const float* bh   = (const float*)d_in[3];
    const float* Wout = (const float*)d_in[4];
    const float* bout = (const float*)d_in[5];
    float* out = (float*)d_out;

    cudaFuncSetAttribute(recur2_kernel,
                         cudaFuncAttributeMaxDynamicSharedMemorySize, R2_SMEM);

    init_kernel<<<256, 256>>>();
    split_w_kernel<<<256, 256>>>(Wih);
    split_x_kernel<<<2048, 256>>>(x);

    dim3 g1(8, 1024);                       // (HD/128, M/128) — n-block fastest
    phase1_mma_kernel<<<g1, 256>>>(bh);

    recur2_kernel<<<128, 128, R2_SMEM>>>(Whh);

    out_kernel<<<dim3(BB, 4), 128>>>(Wout, bout, out);
}

// round 7
// speedup vs baseline: 4.1440x; 1.2607x over previous
#include <cuda_runtime.h>
#include <cuda_bf16.h>
#include <cstdint>
#include <cstddef>

// Problem dims
#define BB   64
#define TT   2048
#define ID   1024
#define HD   1024
#define OD   512

// ---------------------------------------------------------------------------
// Scratch (__device__ globals)
// ---------------------------------------------------------------------------
__device__ float         g_pre[(size_t)TT * BB * HD];        // [t][b][h]  (512 MB)
__device__ __nv_bfloat16 g_abf[(size_t)BB * TT * 2048];      // split X [hi|lo] (512 MB)
__device__ __nv_bfloat16 g_wbf[(size_t)HD * 2048];           // split W_ih [hi|lo] (4 MB)
__device__ __nv_bfloat16 g_hbf[2][2][BB][HD];                // h double-buf, hi/lo (0.5 MB)
__device__ float         g_h[BB * HD];                       // final hidden state
__device__ unsigned      g_cntA[4 * 32];                     // per-group accumulating counters (padded)

// ---------------------------------------------------------------------------
// Generic-PTX helpers (safe for compute_103 target: no tcgen05/TMA)
// ---------------------------------------------------------------------------
__device__ __forceinline__ uint32_t smem_to_u32(const void* p) {
    uint32_t a;
    asm("{ .reg .u64 t; cvta.to.shared.u64 t, %1; cvt.u32.u64 %0, t; }"
        : "=r"(a) : "l"(p));
    return a;
}
__device__ __forceinline__ void cp16(uint32_t saddr, const void* g) {
    asm volatile("cp.async.cg.shared.global [%0], [%1], 16;"
                 :: "r"(saddr), "l"(g) : "memory");
}
#define CP_COMMIT() asm volatile("cp.async.commit_group;" ::: "memory")
#define CP_WAIT1()  asm volatile("cp.async.wait_group 1;" ::: "memory")
#define CP_WAIT0()  asm volatile("cp.async.wait_group 0;" ::: "memory")

__device__ __forceinline__ void ldsm_x4(uint32_t& r0, uint32_t& r1,
                                        uint32_t& r2, uint32_t& r3, uint32_t a) {
    asm volatile("ldmatrix.sync.aligned.m8n8.x4.shared.b16 {%0,%1,%2,%3}, [%4];"
                 : "=r"(r0), "=r"(r1), "=r"(r2), "=r"(r3) : "r"(a));
}
__device__ __forceinline__ void mma16816(float* c, const uint32_t* a,
                                         uint32_t b0, uint32_t b1) {
    asm volatile(
        "mma.sync.aligned.m16n8k16.row.col.f32.bf16.bf16.f32 "
        "{%0,%1,%2,%3}, {%4,%5,%6,%7}, {%8,%9}, {%0,%1,%2,%3};"
        : "+f"(c[0]), "+f"(c[1]), "+f"(c[2]), "+f"(c[3])
        : "r"(a[0]), "r"(a[1]), "r"(a[2]), "r"(a[3]), "r"(b0), "r"(b1));
}

// Accurate tanh built from EX2 (avoids tanh.approx under fast-math)
__device__ __forceinline__ float tanh_acc(float x) {
    float ax = fabsf(x);
    float e  = exp2f(ax * 2.885390081777927f);     // e^{2|x|}
    float r  = 1.0f - 2.0f / (e + 1.0f);
    return (x < 0.0f) ? -r : r;
}

// ---------------------------------------------------------------------------
// init: zero h buffer 0 (hi+lo) and the accumulating barrier counters.
// ---------------------------------------------------------------------------
__global__ __launch_bounds__(256) void init_kernel() {
    unsigned i = blockIdx.x * 256u + threadIdx.x;          // 0..65535
    ((uint32_t*)g_hbf)[i] = 0u;                            // g_hbf[0][*][*][*]
    if (i < 128) g_cntA[i] = 0u;
}

// ---------------------------------------------------------------------------
// bf16 2-term split precompute: rows are [hi(1024) | lo(1024)].
// Phase1 k-tile remap realizes A=[hi|hi|lo], W=[hi|lo|hi] without duplication.
// ---------------------------------------------------------------------------
__device__ __forceinline__ void split4(float4 v, ushort4& h, ushort4& l) {
    __nv_bfloat16 hx = __float2bfloat16(v.x);
    __nv_bfloat16 hy = __float2bfloat16(v.y);
    __nv_bfloat16 hz = __float2bfloat16(v.z);
    __nv_bfloat16 hw = __float2bfloat16(v.w);
    h.x = __bfloat16_as_ushort(hx); h.y = __bfloat16_as_ushort(hy);
    h.z = __bfloat16_as_ushort(hz); h.w = __bfloat16_as_ushort(hw);
    l.x = __bfloat16_as_ushort(__float2bfloat16(v.x - __bfloat162float(hx)));
    l.y = __bfloat16_as_ushort(__float2bfloat16(v.y - __bfloat162float(hy)));
    l.z = __bfloat16_as_ushort(__float2bfloat16(v.z - __bfloat162float(hz)));
    l.w = __bfloat16_as_ushort(__float2bfloat16(v.w - __bfloat162float(hw)));
}

__global__ __launch_bounds__(256) void split_x_kernel(const float* __restrict__ X) {
    const size_t n4 = (size_t)BB * TT * ID / 4;
    size_t stride = (size_t)gridDim.x * blockDim.x;
    for (size_t i = (size_t)blockIdx.x * blockDim.x + threadIdx.x; i < n4; i += stride) {
        size_t m  = i >> 8;
        int    k4 = (int)(i & 255);
        float4 v  = ((const float4*)X)[i];
        ushort4 h, l; split4(v, h, l);
        ushort4* row = (ushort4*)(g_abf + m * 2048);
        row[k4] = h; row[256 + k4] = l;
    }
}

__global__ __launch_bounds__(256) void split_w_kernel(const float* __restrict__ W) {
    const size_t n4 = (size_t)HD * ID / 4;
    size_t stride = (size_t)gridDim.x * blockDim.x;
    for (size_t i = (size_t)blockIdx.x * blockDim.x + threadIdx.x; i < n4; i += stride) {
        size_t m  = i >> 8;
        int    k4 = (int)(i & 255);
        float4 v  = ((const float4*)W)[i];
        ushort4 h, l; split4(v, h, l);
        ushort4* row = (ushort4*)(g_wbf + m * 2048);
        row[k4] = h; row[256 + k4] = l;
    }
}

// ---------------------------------------------------------------------------
// Phase 1 (mma.sync bf16): pre = X @ W_ih^T + b_h.
// K'=3072 logical (96 stages of 32); per-stage k-tile remap into the
// 2048-wide [hi|lo] buffers: A uses [hi, hi, lo], W uses [hi, lo, hi].
// ---------------------------------------------------------------------------
#define P1_STRIDE 40
#define P1_NSTG   96

__global__ __launch_bounds__(256, 2) void phase1_mma_kernel(const float* __restrict__ bh)
{
    __shared__ __nv_bfloat16 As[2][128 * P1_STRIDE];
    __shared__ __nv_bfloat16 Bs[2][128 * P1_STRIDE];

    const int tid  = threadIdx.x;
    const int bn   = blockIdx.x;          // 0..7
    const int bm   = blockIdx.y;          // 0..1023
    const int wid  = tid >> 5, lane = tid & 31;
    const int wm   = wid & 1;
    const int wn   = wid >> 1;

    const __nv_bfloat16* Ag = g_abf + (size_t)(bm * 128) * 2048;
    const __nv_bfloat16* Bg = g_wbf + (size_t)(bn * 128) * 2048;

    const uint32_t sA = smem_to_u32(As);
    const uint32_t sB = smem_to_u32(Bs);
    const int lr = tid >> 2, lq = tid & 3;

    float acc[4][4][4];
#pragma unroll
    for (int i = 0; i < 4; ++i)
#pragma unroll
        for (int j = 0; j < 4; ++j)
#pragma unroll
            for (int k = 0; k < 4; ++k) acc[i][j][k] = 0.0f;

#define LOAD_STAGE(kt, buf) do {                                                  \
    int aoff = (((kt) < 32) ? (kt) : ((kt) - 32)) * 32;                           \
    int woff = (((kt) < 64) ? (kt) : ((kt) - 64)) * 32;                           \
    const __nv_bfloat16* ag = Ag + (size_t)lr * 2048 + aoff + lq * 8;             \
    const __nv_bfloat16* bg = Bg + (size_t)lr * 2048 + woff + lq * 8;             \
    uint32_t da = sA + (uint32_t)(((buf) * 128 + lr) * P1_STRIDE + lq * 8) * 2;   \
    uint32_t db = sB + (uint32_t)(((buf) * 128 + lr) * P1_STRIDE + lq * 8) * 2;   \
    cp16(da, ag); cp16(da + 64 * P1_STRIDE * 2, ag + (size_t)64 * 2048);          \
    cp16(db, bg); cp16(db + 64 * P1_STRIDE * 2, bg + (size_t)64 * 2048);          \
} while (0)

    LOAD_STAGE(0, 0); CP_COMMIT();
    LOAD_STAGE(1, 1); CP_COMMIT();

    const int lrow  = lane & 15;
    const int lhalf = lane >> 4;

    for (int kt = 0; kt < P1_NSTG; ++kt) {
        if (kt < P1_NSTG - 1) { CP_WAIT1(); } else { CP_WAIT0(); }
        __syncthreads();

        const int buf = kt & 1;
        const uint32_t abase = sA + (uint32_t)(buf * 128 * P1_STRIDE) * 2;
        const uint32_t bbase = sB + (uint32_t)(buf * 128 * P1_STRIDE) * 2;

#pragma unroll
        for (int ks = 0; ks < 2; ++ks) {
            uint32_t a[4][4];
#pragma unroll
            for (int mt = 0; mt < 4; ++mt) {
                uint32_t ad = abase +
                    (uint32_t)((wm * 64 + mt * 16 + lrow) * P1_STRIDE + ks * 16 + lhalf * 8) * 2;
                ldsm_x4(a[mt][0], a[mt][1], a[mt][2], a[mt][3], ad);
            }
            uint32_t bf[2][4];
#pragma unroll
            for (int bp = 0; bp < 2; ++bp) {
                uint32_t bd = bbase +
                    (uint32_t)((wn * 32 + bp * 16 + lrow) * P1_STRIDE + ks * 16 + lhalf * 8) * 2;
                ldsm_x4(bf[bp][0], bf[bp][1], bf[bp][2], bf[bp][3], bd);
            }
#pragma unroll
            for (int mt = 0; mt < 4; ++mt)
#pragma unroll
                for (int nt = 0; nt < 4; ++nt)
                    mma16816(acc[mt][nt], a[mt],
                             bf[nt >> 1][nt & 1], bf[nt >> 1][(nt & 1) + 2]);
        }
        __syncthreads();
        if (kt + 2 < P1_NSTG) { LOAD_STAGE(kt + 2, buf); CP_COMMIT(); }
    }
#undef LOAD_STAGE

    const int col0 = bn * 128 + wn * 32;
#pragma unroll
    for (int mt = 0; mt < 4; ++mt) {
#pragma unroll
        for (int half = 0; half < 2; ++half) {
            int m  = bm * 128 + wm * 64 + mt * 16 + (lane >> 2) + half * 8;
            int b_ = m >> 11;
            int t_ = m & (TT - 1);
            float* orow = g_pre + ((size_t)t_ * BB + b_) * HD;
#pragma unroll
            for (int nt = 0; nt < 4; ++nt) {
                int c = col0 + nt * 8 + (lane & 3) * 2;
                float2 v;
                v.x = acc[mt][nt][half * 2 + 0] + __ldg(bh + c);
                v.y = acc[mt][nt][half * 2 + 1] + __ldg(bh + c + 1);
                *(float2*)(orow + c) = v;
            }
        }
    }
}

// ---------------------------------------------------------------------------
// Phase 2: persistent recurrence, flipped-fragment HMMA split-bf16.
// 128 CTAs = 4 batch-groups(16 rows) x 32 col-groups(32 cols), 128 threads.
// Warp(wi,wj): m16 = cols [cg*32+wi*16, +16), n8 = batch [bg*16+wj*8, +8).
// A-fragment = W (own cols, NOT redundant); B-fragment = h (x4 per k32).
// Fused 3-term loop: Wh*hh + Wl*hh + Wh*hl. Barrier = fire-and-forget RED on
// an accumulating per-group counter (target 32*(t+1), never reset).
// ---------------------------------------------------------------------------
#define WS        1032                       // bf16 elems per smem row (129*16B)
#define SM_WHI    0
#define SM_WLO    (32 * WS)
#define SM_HHH    (64 * WS)
#define SM_HHL    (80 * WS)
#define SM_STG    (96 * WS)                  // staging hi [16][40]
#define SM_STG_LO (SM_STG + 16 * 40)         // staging lo [16][40]
#define R2_SMEM   ((96 * WS + 2 * 16 * 40) * 2)   // 200704 bytes

__global__ __launch_bounds__(128, 1) void recur3_kernel(const float* __restrict__ Whh)
{
    extern __shared__ __nv_bfloat16 sm[];
    const int tid  = threadIdx.x;
    const int lane = tid & 31, wid = tid >> 5;
    const int wi   = wid & 1;                // col half (16 cols)
    const int wj   = wid >> 1;               // batch half (8 rows)
    const int bg   = blockIdx.x >> 5;        // 0..3
    const int cg   = blockIdx.x & 31;        // 0..31
    const uint32_t sb = smem_to_u32(sm);

    // ---- persistent W_hh slice [32 cols][1024 k], split hi/lo ----
    for (int e = tid; e < 32 * 1024; e += 128) {
        int n = e >> 10, k = e & 1023;
        float v = Whh[(size_t)(cg * 32 + n) * HD + k];
        __nv_bfloat16 h = __float2bfloat16(v);
        sm[SM_WHI + n * WS + k] = h;
        sm[SM_WLO + n * WS + k] = __float2bfloat16(v - __bfloat162float(h));
    }

    // ldsm base addresses (bytes)
    const uint32_t wRowOff = (uint32_t)((wi * 16 + (lane & 15)) * WS + (lane >> 4) * 8) * 2;
    const uint32_t aWh = sb + SM_WHI * 2 + wRowOff;
    const uint32_t aWl = sb + SM_WLO * 2 + wRowOff;
    const uint32_t hRowOff = (uint32_t)((wj * 8 + (lane & 7)) * WS + (lane >> 3) * 8) * 2;
    const uint32_t aHh = sb + SM_HHH * 2 + hRowOff;
    const uint32_t aHl = sb + SM_HHL * 2 + hRowOff;

    // output coordinates (c-frag: m-row = col, n-col = batch)
    const int mrow  = lane >> 2;             // 0..7
    const int nb0   = (lane & 3) * 2;        // 0,2,4,6
    const int lcol0 = wi * 16 + mrow;        // local col, and +8
    const int lb0   = wj * 8 + nb0;          // local batch, and +1
    const int gcol0 = cg * 32 + lcol0;
    const int gb0   = bg * 16 + lb0;

    volatile unsigned* cntp = (volatile unsigned*)&g_cntA[bg * 32];

    __syncthreads();

    for (int t = 0; t < TT; ++t) {
        const int r = t & 1, w = 1 - r;

        // ---- load h slice (hi+lo) into smem via cp.async ----
#pragma unroll
        for (int s = 0; s < 2; ++s) {
            const __nv_bfloat16* src = &g_hbf[r][s][bg * 16][0];
            uint32_t dst = sb + (uint32_t)(s ? SM_HHL : SM_HHH) * 2;
#pragma unroll
            for (int i = 0; i < 16; ++i) {
                int chunk = tid + i * 128;           // 0..2047
                int row = chunk >> 7, c8 = (chunk & 127) * 8;
                cp16(dst + (uint32_t)(row * WS + c8) * 2, src + row * 1024 + c8);
            }
        }
        CP_COMMIT();

        // pre loads (independent of smem; hide behind cp wait + MMA)
        const float* preb = g_pre + (size_t)t * BB * HD;
        float p0 = preb[(size_t)gb0 * HD + gcol0];
        float p1 = preb[(size_t)(gb0 + 1) * HD + gcol0];
        float p2 = preb[(size_t)gb0 * HD + gcol0 + 8];
        float p3 = preb[(size_t)(gb0 + 1) * HD + gcol0 + 8];

        CP_WAIT0();
        __syncthreads();

        // ---- fused 3-term split GEMM over k=1024 (32 x k32 blocks) ----
        float aA0[4], aA1[4], aB0[4], aB1[4], aC0[4], aC1[4];
#pragma unroll
        for (int j = 0; j < 4; ++j) {
            aA0[j] = aA1[j] = aB0[j] = aB1[j] = aC0[j] = aC1[j] = 0.0f;
        }

#pragma unroll 4
        for (int ks2 = 0; ks2 < 32; ++ks2) {
            const uint32_t ko = (uint32_t)ks2 * 64;
            uint32_t hh[4], hl[4];
            ldsm_x4(hh[0], hh[1], hh[2], hh[3], aHh + ko);
            ldsm_x4(hl[0], hl[1], hl[2], hl[3], aHl + ko);
            uint32_t wh0[4], wl0[4], wh1[4], wl1[4];
            ldsm_x4(wh0[0], wh0[1], wh0[2], wh0[3], aWh + ko);
            ldsm_x4(wl0[0], wl0[1], wl0[2], wl0[3], aWl + ko);
            ldsm_x4(wh1[0], wh1[1], wh1[2], wh1[3], aWh + ko + 32);
            ldsm_x4(wl1[0], wl1[1], wl1[2], wl1[3], aWl + ko + 32);

            mma16816(aA0, wh0, hh[0], hh[1]);
            mma16816(aB0, wl0, hh[0], hh[1]);
            mma16816(aC0, wh0, hl[0], hl[1]);
            mma16816(aA1, wh1, hh[2], hh[3]);
            mma16816(aB1, wl1, hh[2], hh[3]);
            mma16816(aC1, wh1, hl[2], hl[3]);
        }

        float v0 = tanh_acc(((aA0[0] + aA1[0]) + (aB0[0] + aB1[0])) + (aC0[0] + aC1[0]) + p0);
        float v1 = tanh_acc(((aA0[1] + aA1[1]) + (aB0[1] + aB1[1])) + (aC0[1] + aC1[1]) + p1);
        float v2 = tanh_acc(((aA0[2] + aA1[2]) + (aB0[2] + aB1[2])) + (aC0[2] + aC1[2]) + p2);
        float v3 = tanh_acc(((aA0[3] + aA1[3]) + (aB0[3] + aB1[3])) + (aC0[3] + aC1[3]) + p3);

        // ---- split to bf16 hi/lo, stage to smem [16 batch][40 cols] ----
        __nv_bfloat16 h0 = __float2bfloat16(v0), h1 = __float2bfloat16(v1);
        __nv_bfloat16 h2 = __float2bfloat16(v2), h3 = __float2bfloat16(v3);
        sm[SM_STG + lb0 * 40 + lcol0]           = h0;
        sm[SM_STG + (lb0 + 1) * 40 + lcol0]     = h1;
        sm[SM_STG + lb0 * 40 + lcol0 + 8]       = h2;
        sm[SM_STG + (lb0 + 1) * 40 + lcol0 + 8] = h3;
        sm[SM_STG_LO + lb0 * 40 + lcol0]           = __float2bfloat16(v0 - __bfloat162float(h0));
        sm[SM_STG_LO + (lb0 + 1) * 40 + lcol0]     = __float2bfloat16(v1 - __bfloat162float(h1));
        sm[SM_STG_LO + lb0 * 40 + lcol0 + 8]       = __float2bfloat16(v2 - __bfloat162float(h2));
        sm[SM_STG_LO + (lb0 + 1) * 40 + lcol0 + 8] = __float2bfloat16(v3 - __bfloat162float(h3));

        if (t == TT - 1) {
            g_h[(size_t)gb0 * HD + gcol0]           = v0;
            g_h[(size_t)(gb0 + 1) * HD + gcol0]     = v1;
            g_h[(size_t)gb0 * HD + gcol0 + 8]       = v2;
            g_h[(size_t)(gb0 + 1) * HD + gcol0 + 8] = v3;
        }
        __syncthreads();

        // ---- cooperative coalesced store of staged h_next slice ----
        {
            int s = tid >> 6, e = tid & 63;
            int row = e >> 2, c8 = (e & 3) * 8;
            uint4 val = *(const uint4*)&sm[(s ? SM_STG_LO : SM_STG) + row * 40 + c8];
            *(uint4*)&g_hbf[w][s][bg * 16 + row][cg * 32 + c8] = val;
        }

        // ---- barrier: RED arrival + monotonic count poll ----
        __threadfence();
        __syncthreads();
        if (tid == 0) {
            atomicAdd(&g_cntA[bg * 32], 1u);          // result unused -> RED
            const unsigned tgt = 32u * (unsigned)(t + 1);
            while (*cntp < tgt) { }
        }
        __syncthreads();
        __threadfence();
    }
}

// ---------------------------------------------------------------------------
// Phase 3: out[b][o] = h_T[b] . W_out[o] + b_out[o]   grid (64, 4)
// ---------------------------------------------------------------------------
__global__ __launch_bounds__(128) void out_kernel(
    const float* __restrict__ Wout, const float* __restrict__ bout,
    float* __restrict__ out)
{
    __shared__ float hs[HD];
    const int b = blockIdx.x, bo = blockIdx.y, tid = threadIdx.x;
    for (int i = tid; i < HD; i += 128) hs[i] = g_h[(size_t)b * HD + i];
    __syncthreads();
    const int o = bo * 128 + tid;
    const float* w = Wout + (size_t)o * HD;
    float s0 = 0.f, s1 = 0.f, s2 = 0.f, s3 = 0.f;
    for (int k = 0; k < HD; k += 4) {
        float4 wv = *(const float4*)(w + k);
        s0 = fmaf(hs[k + 0], wv.x, s0);
        s1 = fmaf(hs[k + 1], wv.y, s1);
        s2 = fmaf(hs[k + 2], wv.z, s2);
        s3 = fmaf(hs[k + 3], wv.w, s3);
    }
    out[(size_t)b * OD + o] = (s0 + s1) + (s2 + s3) + bout[o];
}

// ---------------------------------------------------------------------------
extern "C" void kernel_launch(void* const* d_in, const int* in_sizes, int n_in,
                              void* d_out, int out_size)
{
    (void)in_sizes; (void)n_in; (void)out_size;
    const float* x    = (const float*)d_in[0];
    const float* Wih  = (const float*)d_in[1];
    const float* Whh  = (const float*)d_in[2];
    const float* bh   = (const float*)d_in[3];
    const float* Wout = (const float*)d_in[4];
    const float* bout = (const float*)d_in[5];
    float* out = (float*)d_out;

    cudaFuncSetAttribute(recur3_kernel,
                         cudaFuncAttributeMaxDynamicSharedMemorySize, R2_SMEM);

    init_kernel<<<256, 256>>>();
    split_w_kernel<<<256, 256>>>(Wih);
    split_x_kernel<<<2048, 256>>>(x);

    dim3 g1(8, 1024);                       // (HD/128, M/128) — n-block fastest
    phase1_mma_kernel<<<g1, 256>>>(bh);

    recur3_kernel<<<128, 128, R2_SMEM>>>(Whh);

    out_kernel<<<dim3(BB, 4), 128>>>(Wout, bout, out);
}

// round 8
// speedup vs baseline: 4.1891x; 1.0109x over previous
#include <cuda_runtime.h>
#include <cuda_bf16.h>
#include <cstdint>
#include <cstddef>

// Problem dims
#define BB   64
#define TT   2048
#define ID   1024
#define HD   1024
#define OD   512

// ---------------------------------------------------------------------------
// Scratch (__device__ globals)
// ---------------------------------------------------------------------------
__device__ float         g_pre[(size_t)TT * BB * HD];        // [t][b][h]  (512 MB)
__device__ __nv_bfloat16 g_abf[(size_t)BB * TT * 2048];      // split X [hi|lo] (512 MB)
__device__ __nv_bfloat16 g_wbf[(size_t)HD * 2048];           // split W_ih [hi|lo] (4 MB)
__device__ __nv_bfloat16 g_hbf[2][2][BB][HD];                // h double-buf, hi/lo (0.5 MB)
__device__ float         g_h[BB * HD];                       // final hidden state
__device__ unsigned      g_cntA[4 * 32];                     // per-group accumulating counters (padded)

// ---------------------------------------------------------------------------
// Generic-PTX helpers (safe for compute_103 target: no tcgen05/TMA)
// ---------------------------------------------------------------------------
__device__ __forceinline__ uint32_t smem_to_u32(const void* p) {
    uint32_t a;
    asm("{ .reg .u64 t; cvta.to.shared.u64 t, %1; cvt.u32.u64 %0, t; }"
        : "=r"(a) : "l"(p));
    return a;
}
__device__ __forceinline__ void cp16(uint32_t saddr, const void* g) {
    asm volatile("cp.async.cg.shared.global [%0], [%1], 16;"
                 :: "r"(saddr), "l"(g) : "memory");
}
#define CP_COMMIT() asm volatile("cp.async.commit_group;" ::: "memory")
#define CP_WAIT1()  asm volatile("cp.async.wait_group 1;" ::: "memory")
#define CP_WAIT0()  asm volatile("cp.async.wait_group 0;" ::: "memory")

__device__ __forceinline__ void ldsm_x4(uint32_t& r0, uint32_t& r1,
                                        uint32_t& r2, uint32_t& r3, uint32_t a) {
    asm volatile("ldmatrix.sync.aligned.m8n8.x4.shared.b16 {%0,%1,%2,%3}, [%4];"
                 : "=r"(r0), "=r"(r1), "=r"(r2), "=r"(r3) : "r"(a));
}
__device__ __forceinline__ void mma16816(float* c, const uint32_t* a,
                                         uint32_t b0, uint32_t b1) {
    asm volatile(
        "mma.sync.aligned.m16n8k16.row.col.f32.bf16.bf16.f32 "
        "{%0,%1,%2,%3}, {%4,%5,%6,%7}, {%8,%9}, {%0,%1,%2,%3};"
        : "+f"(c[0]), "+f"(c[1]), "+f"(c[2]), "+f"(c[3])
        : "r"(a[0]), "r"(a[1]), "r"(a[2]), "r"(a[3]), "r"(b0), "r"(b1));
}

// Accurate tanh built from EX2 (avoids tanh.approx under fast-math)
__device__ __forceinline__ float tanh_acc(float x) {
    float ax = fabsf(x);
    float e  = exp2f(ax * 2.885390081777927f);     // e^{2|x|}
    float r  = 1.0f - 2.0f / (e + 1.0f);
    return (x < 0.0f) ? -r : r;
}

// ---------------------------------------------------------------------------
// init: zero h buffer 0 (hi+lo) and the accumulating barrier counters.
// ---------------------------------------------------------------------------
__global__ __launch_bounds__(256) void init_kernel() {
    unsigned i = blockIdx.x * 256u + threadIdx.x;          // 0..65535
    ((uint32_t*)g_hbf)[i] = 0u;                            // g_hbf[0][*][*][*]
    if (i < 128) g_cntA[i] = 0u;
}

// ---------------------------------------------------------------------------
// bf16 2-term split precompute: rows are [hi(1024) | lo(1024)].
// ---------------------------------------------------------------------------
__device__ __forceinline__ void split4(float4 v, ushort4& h, ushort4& l) {
    __nv_bfloat16 hx = __float2bfloat16(v.x);
    __nv_bfloat16 hy = __float2bfloat16(v.y);
    __nv_bfloat16 hz = __float2bfloat16(v.z);
    __nv_bfloat16 hw = __float2bfloat16(v.w);
    h.x = __bfloat16_as_ushort(hx); h.y = __bfloat16_as_ushort(hy);
    h.z = __bfloat16_as_ushort(hz); h.w = __bfloat16_as_ushort(hw);
    l.x = __bfloat16_as_ushort(__float2bfloat16(v.x - __bfloat162float(hx)));
    l.y = __bfloat16_as_ushort(__float2bfloat16(v.y - __bfloat162float(hy)));
    l.z = __bfloat16_as_ushort(__float2bfloat16(v.z - __bfloat162float(hz)));
    l.w = __bfloat16_as_ushort(__float2bfloat16(v.w - __bfloat162float(hw)));
}

__global__ __launch_bounds__(256) void split_x_kernel(const float* __restrict__ X) {
    const size_t n4 = (size_t)BB * TT * ID / 4;
    size_t stride = (size_t)gridDim.x * blockDim.x;
    for (size_t i = (size_t)blockIdx.x * blockDim.x + threadIdx.x; i < n4; i += stride) {
        size_t m  = i >> 8;
        int    k4 = (int)(i & 255);
        float4 v  = ((const float4*)X)[i];
        ushort4 h, l; split4(v, h, l);
        ushort4* row = (ushort4*)(g_abf + m * 2048);
        row[k4] = h; row[256 + k4] = l;
    }
}

__global__ __launch_bounds__(256) void split_w_kernel(const float* __restrict__ W) {
    const size_t n4 = (size_t)HD * ID / 4;
    size_t stride = (size_t)gridDim.x * blockDim.x;
    for (size_t i = (size_t)blockIdx.x * blockDim.x + threadIdx.x; i < n4; i += stride) {
        size_t m  = i >> 8;
        int    k4 = (int)(i & 255);
        float4 v  = ((const float4*)W)[i];
        ushort4 h, l; split4(v, h, l);
        ushort4* row = (ushort4*)(g_wbf + m * 2048);
        row[k4] = h; row[256 + k4] = l;
    }
}

// ---------------------------------------------------------------------------
// Phase 1 (mma.sync bf16): pre = X @ W_ih^T + b_h.  (unchanged from R7)
// ---------------------------------------------------------------------------
#define P1_STRIDE 40
#define P1_NSTG   96

__global__ __launch_bounds__(256, 2) void phase1_mma_kernel(const float* __restrict__ bh)
{
    __shared__ __nv_bfloat16 As[2][128 * P1_STRIDE];
    __shared__ __nv_bfloat16 Bs[2][128 * P1_STRIDE];

    const int tid  = threadIdx.x;
    const int bn   = blockIdx.x;          // 0..7
    const int bm   = blockIdx.y;          // 0..1023
    const int wid  = tid >> 5, lane = tid & 31;
    const int wm   = wid & 1;
    const int wn   = wid >> 1;

    const __nv_bfloat16* Ag = g_abf + (size_t)(bm * 128) * 2048;
    const __nv_bfloat16* Bg = g_wbf + (size_t)(bn * 128) * 2048;

    const uint32_t sA = smem_to_u32(As);
    const uint32_t sB = smem_to_u32(Bs);
    const int lr = tid >> 2, lq = tid & 3;

    float acc[4][4][4];
#pragma unroll
    for (int i = 0; i < 4; ++i)
#pragma unroll
        for (int j = 0; j < 4; ++j)
#pragma unroll
            for (int k = 0; k < 4; ++k) acc[i][j][k] = 0.0f;

#define LOAD_STAGE(kt, buf) do {                                                  \
    int aoff = (((kt) < 32) ? (kt) : ((kt) - 32)) * 32;                           \
    int woff = (((kt) < 64) ? (kt) : ((kt) - 64)) * 32;                           \
    const __nv_bfloat16* ag = Ag + (size_t)lr * 2048 + aoff + lq * 8;             \
    const __nv_bfloat16* bg = Bg + (size_t)lr * 2048 + woff + lq * 8;             \
    uint32_t da = sA + (uint32_t)(((buf) * 128 + lr) * P1_STRIDE + lq * 8) * 2;   \
    uint32_t db = sB + (uint32_t)(((buf) * 128 + lr) * P1_STRIDE + lq * 8) * 2;   \
    cp16(da, ag); cp16(da + 64 * P1_STRIDE * 2, ag + (size_t)64 * 2048);          \
    cp16(db, bg); cp16(db + 64 * P1_STRIDE * 2, bg + (size_t)64 * 2048);          \
} while (0)

    LOAD_STAGE(0, 0); CP_COMMIT();
    LOAD_STAGE(1, 1); CP_COMMIT();

    const int lrow  = lane & 15;
    const int lhalf = lane >> 4;

    for (int kt = 0; kt < P1_NSTG; ++kt) {
        if (kt < P1_NSTG - 1) { CP_WAIT1(); } else { CP_WAIT0(); }
        __syncthreads();

        const int buf = kt & 1;
        const uint32_t abase = sA + (uint32_t)(buf * 128 * P1_STRIDE) * 2;
        const uint32_t bbase = sB + (uint32_t)(buf * 128 * P1_STRIDE) * 2;

#pragma unroll
        for (int ks = 0; ks < 2; ++ks) {
            uint32_t a[4][4];
#pragma unroll
            for (int mt = 0; mt < 4; ++mt) {
                uint32_t ad = abase +
                    (uint32_t)((wm * 64 + mt * 16 + lrow) * P1_STRIDE + ks * 16 + lhalf * 8) * 2;
                ldsm_x4(a[mt][0], a[mt][1], a[mt][2], a[mt][3], ad);
            }
            uint32_t bf[2][4];
#pragma unroll
            for (int bp = 0; bp < 2; ++bp) {
                uint32_t bd = bbase +
                    (uint32_t)((wn * 32 + bp * 16 + lrow) * P1_STRIDE + ks * 16 + lhalf * 8) * 2;
                ldsm_x4(bf[bp][0], bf[bp][1], bf[bp][2], bf[bp][3], bd);
            }
#pragma unroll
            for (int mt = 0; mt < 4; ++mt)
#pragma unroll
                for (int nt = 0; nt < 4; ++nt)
                    mma16816(acc[mt][nt], a[mt],
                             bf[nt >> 1][nt & 1], bf[nt >> 1][(nt & 1) + 2]);
        }
        __syncthreads();
        if (kt + 2 < P1_NSTG) { LOAD_STAGE(kt + 2, buf); CP_COMMIT(); }
    }
#undef LOAD_STAGE

    const int col0 = bn * 128 + wn * 32;
#pragma unroll
    for (int mt = 0; mt < 4; ++mt) {
#pragma unroll
        for (int half = 0; half < 2; ++half) {
            int m  = bm * 128 + wm * 64 + mt * 16 + (lane >> 2) + half * 8;
            int b_ = m >> 11;
            int t_ = m & (TT - 1);
            float* orow = g_pre + ((size_t)t_ * BB + b_) * HD;
#pragma unroll
            for (int nt = 0; nt < 4; ++nt) {
                int c = col0 + nt * 8 + (lane & 3) * 2;
                float2 v;
                v.x = acc[mt][nt][half * 2 + 0] + __ldg(bh + c);
                v.y = acc[mt][nt][half * 2 + 1] + __ldg(bh + c + 1);
                *(float2*)(orow + c) = v;
            }
        }
    }
}

// ---------------------------------------------------------------------------
// Phase 2: persistent recurrence, 256 threads/CTA, intra-CTA k-split.
// 128 CTAs = 4 batch-groups(16 rows) x 32 col-groups(32 cols).
// 8 warps = 2 warpsets: set0 k[0,512), set1 k[512,1024); within a set,
// warp(wi,wj): m16 = W cols [wi*16,+16), n8 = batch [wj*8,+8).
// Partials -> float smem staging; 256-thread combine: +pre, tanh, split,
// coalesced bf16 store. Barrier = RED on accumulating per-group counter.
// ---------------------------------------------------------------------------
#define WS        1032                       // bf16 elems per smem row (129*16B)
#define SM_WHI    0
#define SM_WLO    (32 * WS)
#define SM_HHH    (64 * WS)
#define SM_HHL    (80 * WS)
#define SM_STGF   (96 * WS)                  // float staging [2][16][33] after this
#define R4_SMEM   (96 * WS * 2 + 2 * 16 * 33 * 4)   // 198144 + 4224 = 202368

__global__ __launch_bounds__(256, 1) void recur4_kernel(const float* __restrict__ Whh)
{
    extern __shared__ __nv_bfloat16 sm[];
    float* stg = (float*)&sm[SM_STGF];       // [2][16][33]
    const int tid  = threadIdx.x;
    const int lane = tid & 31, wid = tid >> 5;
    const int wset = wid >> 2;               // k-half
    const int w4   = wid & 3;
    const int wi   = w4 & 1;                 // col half (16 cols)
    const int wj   = w4 >> 1;                // batch half (8 rows)
    const int bg   = blockIdx.x >> 5;        // 0..3
    const int cg   = blockIdx.x & 31;        // 0..31
    const uint32_t sb = smem_to_u32(sm);

    // ---- persistent W_hh slice [32 cols][1024 k], split hi/lo ----
    for (int e = tid; e < 32 * 1024; e += 256) {
        int n = e >> 10, k = e & 1023;
        float v = Whh[(size_t)(cg * 32 + n) * HD + k];
        __nv_bfloat16 h = __float2bfloat16(v);
        sm[SM_WHI + n * WS + k] = h;
        sm[SM_WLO + n * WS + k] = __float2bfloat16(v - __bfloat162float(h));
    }

    // ldsm base addresses (bytes); kbase selects this warpset's k-half
    const uint32_t kbase = (uint32_t)wset * 1024;   // 512 elems * 2B
    const uint32_t wRowOff = (uint32_t)((wi * 16 + (lane & 15)) * WS + (lane >> 4) * 8) * 2;
    const uint32_t aWh = sb + SM_WHI * 2 + wRowOff + kbase;
    const uint32_t aWl = sb + SM_WLO * 2 + wRowOff + kbase;
    const uint32_t hRowOff = (uint32_t)((wj * 8 + (lane & 7)) * WS + (lane >> 3) * 8) * 2;
    const uint32_t aHh = sb + SM_HHH * 2 + hRowOff + kbase;
    const uint32_t aHl = sb + SM_HHL * 2 + hRowOff + kbase;

    // warp output coordinates in the local 32col x 16batch tile
    const int mrow  = lane >> 2;             // 0..7
    const int nb0   = (lane & 3) * 2;        // 0,2,4,6
    const int lcol0 = wi * 16 + mrow;        // local col, and +8
    const int lb0   = wj * 8 + nb0;          // local batch, and +1
    float* stgw = stg + wset * 16 * 33;

    // combine-phase coordinates (one float2 per thread)
    const int cb   = tid >> 4;               // 0..15 local batch
    const int cc   = (tid & 15) * 2;         // 0..30 local col pair
    const int gb   = bg * 16 + cb;
    const int gc   = cg * 32 + cc;

    volatile unsigned* cntp = (volatile unsigned*)&g_cntA[bg * 32];

    __syncthreads();

    for (int t = 0; t < TT; ++t) {
        const int r = t & 1, w = 1 - r;

        // ---- load h slice (hi+lo) into smem via cp.async (256 threads) ----
#pragma unroll
        for (int s = 0; s < 2; ++s) {
            const __nv_bfloat16* src = &g_hbf[r][s][bg * 16][0];
            uint32_t dst = sb + (uint32_t)(s ? SM_HHL : SM_HHH) * 2;
#pragma unroll
            for (int i = 0; i < 8; ++i) {
                int chunk = tid + i * 256;           // 0..2047
                int row = chunk >> 7, c8 = (chunk & 127) * 8;
                cp16(dst + (uint32_t)(row * WS + c8) * 2, src + row * 1024 + c8);
            }
        }
        CP_COMMIT();

        // prefetch pre for the combine phase (hidden behind cp wait + MMA)
        const float2 pv = *(const float2*)&g_pre[((size_t)t * BB + gb) * HD + gc];

        CP_WAIT0();
        __syncthreads();

        // ---- fused 3-term split GEMM over this warpset's k-half ----
        float aA0[4], aA1[4], aB0[4], aB1[4], aC0[4], aC1[4];
#pragma unroll
        for (int j = 0; j < 4; ++j) {
            aA0[j] = aA1[j] = aB0[j] = aB1[j] = aC0[j] = aC1[j] = 0.0f;
        }

#pragma unroll 4
        for (int ks2 = 0; ks2 < 16; ++ks2) {
            const uint32_t ko = (uint32_t)ks2 * 64;
            uint32_t hh[4], hl[4];
            ldsm_x4(hh[0], hh[1], hh[2], hh[3], aHh + ko);
            ldsm_x4(hl[0], hl[1], hl[2], hl[3], aHl + ko);
            uint32_t wh0[4], wl0[4], wh1[4], wl1[4];
            ldsm_x4(wh0[0], wh0[1], wh0[2], wh0[3], aWh + ko);
            ldsm_x4(wl0[0], wl0[1], wl0[2], wl0[3], aWl + ko);
            ldsm_x4(wh1[0], wh1[1], wh1[2], wh1[3], aWh + ko + 32);
            ldsm_x4(wl1[0], wl1[1], wl1[2], wl1[3], aWl + ko + 32);

            mma16816(aA0, wh0, hh[0], hh[1]);
            mma16816(aB0, wl0, hh[0], hh[1]);
            mma16816(aC0, wh0, hl[0], hl[1]);
            mma16816(aA1, wh1, hh[2], hh[3]);
            mma16816(aB1, wl1, hh[2], hh[3]);
            mma16816(aC1, wh1, hl[2], hl[3]);
        }

        // ---- stage this warpset's partial sums ----
#pragma unroll
        for (int j = 0; j < 4; ++j) {
            float cj = ((aA0[j] + aA1[j]) + (aB0[j] + aB1[j])) + (aC0[j] + aC1[j]);
            int bb_ = lb0 + (j & 1);
            int cc_ = lcol0 + (j >> 1) * 8;
            stgw[bb_ * 33 + cc_] = cj;
        }
        __syncthreads();

        // ---- combine: set0 + set1 + pre -> tanh -> split -> store ----
        {
            float v0 = tanh_acc(stg[cb * 33 + cc]     + stg[16 * 33 + cb * 33 + cc]     + pv.x);
            float v1 = tanh_acc(stg[cb * 33 + cc + 1] + stg[16 * 33 + cb * 33 + cc + 1] + pv.y);

            __nv_bfloat16 h0 = __float2bfloat16(v0), h1 = __float2bfloat16(v1);
            __nv_bfloat162 hi2; hi2.x = h0; hi2.y = h1;
            __nv_bfloat162 lo2;
            lo2.x = __float2bfloat16(v0 - __bfloat162float(h0));
            lo2.y = __float2bfloat16(v1 - __bfloat162float(h1));

            *(__nv_bfloat162*)&g_hbf[w][0][gb][gc] = hi2;
            *(__nv_bfloat162*)&g_hbf[w][1][gb][gc] = lo2;

            if (t == TT - 1)
                *(float2*)&g_h[(size_t)gb * HD + gc] = make_float2(v0, v1);
        }

        // ---- barrier: RED arrival + monotonic count poll ----
        __threadfence();
        __syncthreads();
        if (tid == 0) {
            atomicAdd(&g_cntA[bg * 32], 1u);          // result unused -> RED
            const unsigned tgt = 32u * (unsigned)(t + 1);
            while (*cntp < tgt) { }
        }
        __syncthreads();
        __threadfence();
    }
}

// ---------------------------------------------------------------------------
// Phase 3: out[b][o] = h_T[b] . W_out[o] + b_out[o]   grid (64, 4)
// ---------------------------------------------------------------------------
__global__ __launch_bounds__(128) void out_kernel(
    const float* __restrict__ Wout, const float* __restrict__ bout,
    float* __restrict__ out)
{
    __shared__ float hs[HD];
    const int b = blockIdx.x, bo = blockIdx.y, tid = threadIdx.x;
    for (int i = tid; i < HD; i += 128) hs[i] = g_h[(size_t)b * HD + i];
    __syncthreads();
    const int o = bo * 128 + tid;
    const float* w = Wout + (size_t)o * HD;
    float s0 = 0.f, s1 = 0.f, s2 = 0.f, s3 = 0.f;
    for (int k = 0; k < HD; k += 4) {
        float4 wv = *(const float4*)(w + k);
        s0 = fmaf(hs[k + 0], wv.x, s0);
        s1 = fmaf(hs[k + 1], wv.y, s1);
        s2 = fmaf(hs[k + 2], wv.z, s2);
        s3 = fmaf(hs[k + 3], wv.w, s3);
    }
    out[(size_t)b * OD + o] = (s0 + s1) + (s2 + s3) + bout[o];
}

// ---------------------------------------------------------------------------
extern "C" void kernel_launch(void* const* d_in, const int* in_sizes, int n_in,
                              void* d_out, int out_size)
{
    (void)in_sizes; (void)n_in; (void)out_size;
    const float* x    = (const float*)d_in[0];
    const float* Wih  = (const float*)d_in[1];
    const float* Whh  = (const float*)d_in[2];
    const float* bh   = (const float*)d_in[3];
    const float* Wout = (const float*)d_in[4];
    const float* bout = (const float*)d_in[5];
    float* out = (float*)d_out;

    cudaFuncSetAttribute(recur4_kernel,
                         cudaFuncAttributeMaxDynamicSharedMemorySize, R4_SMEM);

    init_kernel<<<256, 256>>>();
    split_w_kernel<<<256, 256>>>(Wih);
    split_x_kernel<<<2048, 256>>>(x);

    dim3 g1(8, 1024);                       // (HD/128, M/128) — n-block fastest
    phase1_mma_kernel<<<g1, 256>>>(bh);

    recur4_kernel<<<128, 256, R4_SMEM>>>(Whh);

    out_kernel<<<dim3(BB, 4), 128>>>(Wout, bout, out);
}